// round 8
// baseline (speedup 1.0000x reference)
#include <cuda_runtime.h>
#include <cstdint>

#define BATCH 8
#define NPTS  8192
#define CFEAT 64
#define SPTS  1024      // NPOINT
#define KS    32        // NSAMPLE
#define CIN0  67        // 3 + CFEAT
#define O0    64
#define O1    64
#define O2    128
#define MTOT  (BATCH*SPTS*KS)   // 262144
#define NPART (MTOT/128)        // 2048 per-warp stat partials

// ---------------- scratch (static device globals; no allocations) ----------
__device__ __align__(128) float g_scratch[(size_t)(CIN0 + O0 + O1 + O2) * MTOT];
__device__ __align__(128) float g_featT[(size_t)BATCH * NPTS * CFEAT];
__device__ __align__(128) float g_part[(size_t)NPART * O2 * 2];
__device__ __align__(128) int   g_idx[BATCH * SPTS * KS];
__device__ __align__(128) float g_aff[3 * 256];   // per layer: a[0..127], b'[128..255]

// ----------------------------- f32x2 helpers -------------------------------
typedef unsigned long long ull;
__device__ __forceinline__ ull pk2(float lo, float hi) {
    ull r; asm("mov.b64 %0, {%1,%2};" : "=l"(r) : "f"(lo), "f"(hi)); return r;
}
__device__ __forceinline__ void upk2(ull v, float& lo, float& hi) {
    asm("mov.b64 {%0,%1}, %2;" : "=f"(lo), "=f"(hi) : "l"(v));
}
__device__ __forceinline__ ull add2(ull a, ull b) {
    ull r; asm("add.rn.f32x2 %0, %1, %2;" : "=l"(r) : "l"(a), "l"(b)); return r;
}
__device__ __forceinline__ ull mul2(ull a, ull b) {
    ull r; asm("mul.rn.f32x2 %0, %1, %2;" : "=l"(r) : "l"(a), "l"(b)); return r;
}
__device__ __forceinline__ ull fma2(ull a, ull b, ull c) {
    ull r; asm("fma.rn.f32x2 %0, %1, %2, %3;" : "=l"(r) : "l"(a), "l"(b), "l"(c)); return r;
}
__device__ __forceinline__ ull umax64(ull a, ull b) { return a > b ? a : b; }

// dummy kernels to align the ncu capture window onto fps_kernel
__global__ void dummy_kernel() {}

// ---------------------------------------------------------------------------
// 1) Farthest point sampling: one CTA per batch, 512 threads, 16 pts/thread.
//    Packed f32x2 distance arithmetic, ONE barrier per iteration via parity
//    double-buffered packed (val, ~idx) keys; branchless leader-lane scan.
// ---------------------------------------------------------------------------
#define FPT 16          // points per thread
#define FTH 512         // threads
#define FWP (FTH/32)    // 16 warps

__global__ __launch_bounds__(FTH, 1) void fps_kernel(const float* __restrict__ xyz,
                                                     float* __restrict__ out_xyz)
{
    extern __shared__ float sm[];
    float* sx = sm;
    float* sy = sm + NPTS;
    float* sz = sm + 2 * NPTS;
    __shared__ __align__(16) ull s_wk[2][FWP];

    const int b = blockIdx.x;
    const int t = threadIdx.x;
    const int lane = t & 31, wid = t >> 5;
    const float* base = xyz + (size_t)b * NPTS * 3;

    for (int j = t; j < NPTS; j += FTH) {
        sx[j] = base[3 * j + 0];
        sy[j] = base[3 * j + 1];
        sz[j] = base[3 * j + 2];
    }
    __syncthreads();

    const int i0 = t * FPT;
    ull px2[FPT / 2], py2[FPT / 2], pz2[FPT / 2];
    float dist[FPT];
#pragma unroll
    for (int i = 0; i < FPT / 2; i++) {
        px2[i] = pk2(sx[i0 + 2 * i], sx[i0 + 2 * i + 1]);
        py2[i] = pk2(sy[i0 + 2 * i], sy[i0 + 2 * i + 1]);
        pz2[i] = pk2(sz[i0 + 2 * i], sz[i0 + 2 * i + 1]);
    }
#pragma unroll
    for (int i = 0; i < FPT; i++) dist[i] = 1e10f;

    int far = 0;
    for (int it = 0; it < SPTS; ++it) {
        const float cx = sx[far], cy = sy[far], cz = sz[far];
        if (t == 0) {
            float* o = out_xyz + ((size_t)b * SPTS + it) * 3;
            o[0] = cx; o[1] = cy; o[2] = cz;
        }
        const ull ncx = pk2(-cx, -cx), ncy = pk2(-cy, -cy), ncz = pk2(-cz, -cz);
        float bv0 = 0.0f, bv1 = 0.0f;    // dists >= 0, 0 is identity; split chains
#pragma unroll
        for (int i = 0; i < FPT / 2; i++) {
            const ull dx = add2(px2[i], ncx);
            const ull dy = add2(py2[i], ncy);
            const ull dz = add2(pz2[i], ncz);
            ull tt = mul2(dx, dx);
            tt = fma2(dy, dy, tt);
            tt = fma2(dz, dz, tt);          // same per-lane rounding/assoc as scalar FMA form
            float d0, d1; upk2(tt, d0, d1); // free: register-pair aliasing
            const float n0 = fminf(dist[2 * i],     d0);
            const float n1 = fminf(dist[2 * i + 1], d1);
            dist[2 * i] = n0; dist[2 * i + 1] = n1;
            bv0 = fmaxf(bv0, n0);
            bv1 = fmaxf(bv1, n1);
        }
        const float bv = fmaxf(bv0, bv1);
        const unsigned key = __float_as_uint(bv);           // bv >= 0 -> monotonic as uint
        const unsigned wmx = __reduce_max_sync(0xffffffffu, key);
        const unsigned bal = __ballot_sync(0xffffffffu, key == wmx);
        const int p = it & 1;
        if (lane == __ffs(bal) - 1) {                       // lowest lane = lowest i0 on tie
            int nidx = 0x7fffffff;                          // branchless lowest-match scan
#pragma unroll
            for (int i = 0; i < FPT; i++)
                if (__float_as_uint(dist[i]) == wmx) nidx = min(nidx, i0 + i);
            s_wk[p][wid] = ((ull)wmx << 32) | (unsigned)(0x7fffffff - nidx);
        }
        __syncthreads();                                    // the ONLY barrier per iteration

        const ulonglong2* wk = (const ulonglong2*)s_wk[p];
        ull best = 0;
#pragma unroll
        for (int i = 0; i < FWP / 2; i++) {
            const ulonglong2 v = wk[i];
            best = umax64(best, umax64(v.x, v.y));
        }
        far = 0x7fffffff - (int)(unsigned)(best & 0xffffffffu);   // smallest idx on value tie
    }
}

// ---------------------------------------------------------------------------
// 2) Ball query: one warp per centroid; ballot-prefix compaction, early exit.
// ---------------------------------------------------------------------------
__global__ __launch_bounds__(256) void ballquery_kernel(const float* __restrict__ xyz,
                                                        const float* __restrict__ new_xyz,
                                                        int* __restrict__ idx)
{
    const int warpg = blockIdx.x * 8 + (threadIdx.x >> 5);
    const int lane  = threadIdx.x & 31;
    const int b = warpg >> 10;
    const int s = warpg & 1023;

    const float* nx = new_xyz + ((size_t)b * SPTS + s) * 3;
    const float cx = nx[0], cy = nx[1], cz = nx[2];
    const float* base = xyz + (size_t)b * NPTS * 3;
    int* out = idx + (size_t)(b * SPTS + s) * KS;
    const float R2 = 0.04f;

    int cnt = 0, first = -1;
    for (int j0 = 0; j0 < NPTS; j0 += 32) {
        const int j = j0 + lane;
        float dx = base[3 * j + 0] - cx;
        float dy = base[3 * j + 1] - cy;
        float dz = base[3 * j + 2] - cz;
        float d = dx * dx + dy * dy + dz * dz;
        bool in = (d <= R2);
        unsigned bal = __ballot_sync(0xffffffffu, in);
        if (first < 0 && bal) first = j0 + __ffs(bal) - 1;
        int pos = cnt + __popc(bal & ((1u << lane) - 1u));
        if (in && pos < KS) out[pos] = j;
        cnt += __popc(bal);
        if (cnt >= KS) break;
    }
    for (int p = cnt + lane; p < KS; p += 32) out[p] = first;
}

// ---------------------------------------------------------------------------
// 2b) Feature transpose: feat[B][C][N] -> featT[B][N][C] (C=64 contiguous)
// ---------------------------------------------------------------------------
__global__ __launch_bounds__(256) void transpose_kernel(const float* __restrict__ feat,
                                                        float* __restrict__ featT)
{
    __shared__ float tile[64][33];
    const int blk = blockIdx.x;           // B * (NPTS/32) blocks
    const int b  = blk >> 8;
    const int n0 = (blk & 255) * 32;
    const int t  = threadIdx.x;
    const int wid = t >> 5, lane = t & 31;

    const float* src = feat + (size_t)b * CFEAT * NPTS + n0;
#pragma unroll
    for (int r = 0; r < 8; r++) {
        const int c = r * 8 + wid;
        tile[c][lane] = src[(size_t)c * NPTS + lane];
    }
    __syncthreads();
    const int c  = t & 63;
    const int ns = t >> 6;
    float* dst = featT + ((size_t)b * NPTS + n0) * 64 + c;
#pragma unroll
    for (int j = 0; j < 8; j++) {
        const int n = ns + j * 4;
        dst[(size_t)n * 64] = tile[c][n];
    }
}

// ---------------------------------------------------------------------------
// 3) Grouping: build X0[c][m], m=(b*S+s)*K+k; contiguous 256B feature rows.
// ---------------------------------------------------------------------------
__global__ __launch_bounds__(256) void group_kernel(const float* __restrict__ xyz,
                                                    const float* __restrict__ featT,
                                                    const float* __restrict__ new_xyz,
                                                    const int* __restrict__ idx,
                                                    float* __restrict__ X)
{
    const int m = blockIdx.x * 256 + threadIdx.x;
    const int b = m >> 15;
    const int s = (m >> 5) & 1023;
    const int i = idx[m];

    const float* p  = xyz + ((size_t)b * NPTS + i) * 3;
    const float* nx = new_xyz + ((size_t)b * SPTS + s) * 3;
    X[0 * (size_t)MTOT + m] = p[0] - nx[0];
    X[1 * (size_t)MTOT + m] = p[1] - nx[1];
    X[2 * (size_t)MTOT + m] = p[2] - nx[2];

    const float4* f = (const float4*)(featT + ((size_t)b * NPTS + i) * 64);
#pragma unroll
    for (int j = 0; j < 16; j++) {
        const float4 v = f[j];
        X[(size_t)(3 + 4 * j + 0) * MTOT + m] = v.x;
        X[(size_t)(3 + 4 * j + 1) * MTOT + m] = v.y;
        X[(size_t)(3 + 4 * j + 2) * MTOT + m] = v.z;
        X[(size_t)(3 + 4 * j + 3) * MTOT + m] = v.w;
    }
}

// ---------------------------------------------------------------------------
// 4) GEMM: Y[o][m] = sum_c W[o][c] * relu?(a_c x + b'_c) + bias[o]
//    Tile 16(o) x 4(m) per thread, 2 CTAs/SM, depth-2 x prefetch.
//    Epilogue emits per-warp per-channel (sum, sumsq) partials (deterministic).
// ---------------------------------------------------------------------------
template <int CIN, int OUT, bool TR>
__global__ __launch_bounds__(256, 2) void gemm_kernel(const float* __restrict__ Xin,
                                                      const float* __restrict__ W,
                                                      const float* __restrict__ bias,
                                                      const float* __restrict__ aff,
                                                      float* __restrict__ Y,
                                                      float* __restrict__ part)
{
    __shared__ float sW[CIN * OUT];
    __shared__ float sA[TR ? CIN : 1];
    __shared__ float sB[TR ? CIN : 1];

    const int t = threadIdx.x;
    for (int i = t; i < CIN * OUT; i += 256) {
        const int c = i / OUT, o = i % OUT;
        sW[i] = W[o * CIN + c];            // transpose: sW[c][o]
    }
    if (TR) {
        for (int c = t; c < CIN; c += 256) { sA[c] = aff[c]; sB[c] = aff[128 + c]; }
    }
    __syncthreads();

    constexpr int OC   = OUT / 16;          // o-chunks per block
    constexpr int MW   = 8 / OC;            // m-warps per block
    constexpr int MBLK = MW * 128;
    const int warp = t >> 5, lane = t & 31;
    const int ow = warp % OC, mw = warp / OC;
    const int m0 = blockIdx.x * MBLK + mw * 128 + lane * 4;
    const int o0 = ow * 16;

    float acc[16][4];
#pragma unroll
    for (int oo = 0; oo < 16; oo++) {
        const float bv = bias[o0 + oo];
#pragma unroll
        for (int mm = 0; mm < 4; mm++) acc[oo][mm] = bv;
    }

    const float* xp = Xin + m0;
    float4 xv = *(const float4*)(xp);
    float4 xn = *(const float4*)(xp + (size_t)MTOT);

#pragma unroll 4
    for (int c = 0; c < CIN; c++) {
        const float4 xf = xv;
        xv = xn;
        if (c + 2 < CIN) xn = *(const float4*)(xp + (size_t)(c + 2) * MTOT);

        float xs[4] = {xf.x, xf.y, xf.z, xf.w};
        if (TR) {
            const float a = sA[c], bb = sB[c];
#pragma unroll
            for (int mm = 0; mm < 4; mm++) xs[mm] = fmaxf(fmaf(a, xs[mm], bb), 0.0f);
        }
        const float4* wp = (const float4*)(sW + c * OUT + o0);
        const float4 w0 = wp[0], w1 = wp[1], w2 = wp[2], w3 = wp[3];
        const float ws[16] = {w0.x, w0.y, w0.z, w0.w, w1.x, w1.y, w1.z, w1.w,
                              w2.x, w2.y, w2.z, w2.w, w3.x, w3.y, w3.z, w3.w};
#pragma unroll
        for (int oo = 0; oo < 16; oo++)
#pragma unroll
            for (int mm = 0; mm < 4; mm++)
                acc[oo][mm] = fmaf(ws[oo], xs[mm], acc[oo][mm]);
    }

    const int pidx = blockIdx.x * MW + mw;   // 0..NPART-1 (each warp owns 128 m)
#pragma unroll
    for (int oo = 0; oo < 16; oo++) {
        float* yp = Y + (size_t)(o0 + oo) * MTOT + m0;
        *(float4*)yp = make_float4(acc[oo][0], acc[oo][1], acc[oo][2], acc[oo][3]);

        float s = (acc[oo][0] + acc[oo][1]) + (acc[oo][2] + acc[oo][3]);
        float q = fmaf(acc[oo][0], acc[oo][0], fmaf(acc[oo][1], acc[oo][1],
                  fmaf(acc[oo][2], acc[oo][2], acc[oo][3] * acc[oo][3])));
#pragma unroll
        for (int d = 16; d > 0; d >>= 1) {
            s += __shfl_down_sync(0xffffffffu, s, d);
            q += __shfl_down_sync(0xffffffffu, q, d);
        }
        if (lane == 0) {
            float* pp = part + ((size_t)pidx * OUT + (o0 + oo)) * 2;
            pp[0] = s; pp[1] = q;
        }
    }
}

// ---------------------------------------------------------------------------
// 5) Reduce per-warp partials -> folded BN affine (a, b')
// ---------------------------------------------------------------------------
template <int OUT>
__global__ __launch_bounds__(256) void stats2_kernel(const float* __restrict__ part,
                                                     const float* __restrict__ g,
                                                     const float* __restrict__ beta,
                                                     float* __restrict__ aff)
{
    const int c = blockIdx.x;
    float s = 0.0f, q = 0.0f;
    for (int p = threadIdx.x; p < NPART; p += 256) {
        const float* pp = part + ((size_t)p * OUT + c) * 2;
        s += pp[0]; q += pp[1];
    }
    __shared__ float rs[256], rq[256];
    rs[threadIdx.x] = s; rq[threadIdx.x] = q;
    __syncthreads();
    for (int st = 128; st > 0; st >>= 1) {
        if (threadIdx.x < st) {
            rs[threadIdx.x] += rs[threadIdx.x + st];
            rq[threadIdx.x] += rq[threadIdx.x + st];
        }
        __syncthreads();
    }
    if (threadIdx.x == 0) {
        const float mean = rs[0] / (float)MTOT;
        float var = rq[0] / (float)MTOT - mean * mean;
        var = fmaxf(var, 0.0f);
        const float r = rsqrtf(var + 1e-5f);
        const float a = g[c] * r;
        aff[c]       = a;
        aff[128 + c] = beta[c] - mean * a;
    }
}

// ---------------------------------------------------------------------------
// 6) Max pool over K with fused final BN+ReLU
// ---------------------------------------------------------------------------
__global__ __launch_bounds__(256) void maxpool_kernel(const float* __restrict__ Y2,
                                                      const float* __restrict__ aff,
                                                      float* __restrict__ out)
{
    const int gid = blockIdx.x * 256 + threadIdx.x;  // ((b*128)+o)*1024+s
    const int s = gid & 1023;
    const int o = (gid >> 10) & 127;
    const int b = gid >> 17;
    const float a = aff[o], bb = aff[128 + o];
    const float4* p = (const float4*)(Y2 + (size_t)o * MTOT + (size_t)(b * SPTS + s) * KS);
    float mx = __int_as_float(0xff800000);
#pragma unroll
    for (int j = 0; j < 8; j++) {
        const float4 v = p[j];
        mx = fmaxf(mx, fmaf(a, v.x, bb));
        mx = fmaxf(mx, fmaf(a, v.y, bb));
        mx = fmaxf(mx, fmaf(a, v.z, bb));
        mx = fmaxf(mx, fmaf(a, v.w, bb));
    }
    out[((size_t)b * O2 + o) * SPTS + s] = fmaxf(mx, 0.0f);
}

// ---------------------------------------------------------------------------
extern "C" void kernel_launch(void* const* d_in, const int* in_sizes, int n_in,
                              void* d_out, int out_size)
{
    const float* xyz  = (const float*)d_in[0];
    const float* feat = (const float*)d_in[1];
    const float* W0   = (const float*)d_in[2];
    const float* b0   = (const float*)d_in[3];
    const float* g0   = (const float*)d_in[4];
    const float* be0  = (const float*)d_in[5];
    const float* W1   = (const float*)d_in[6];
    const float* b1   = (const float*)d_in[7];
    const float* g1   = (const float*)d_in[8];
    const float* be1  = (const float*)d_in[9];
    const float* W2   = (const float*)d_in[10];
    const float* b2   = (const float*)d_in[11];
    const float* g2   = (const float*)d_in[12];
    const float* be2  = (const float*)d_in[13];

    float* out      = (float*)d_out;
    float* new_xyz  = out;                       // [B, S, 3]
    float* new_feat = out + BATCH * SPTS * 3;    // [B, 128, S]

    float* scratch = nullptr; float* featT = nullptr; float* partp = nullptr;
    int* idxp = nullptr; float* affp = nullptr;
    cudaGetSymbolAddress((void**)&scratch, g_scratch);
    cudaGetSymbolAddress((void**)&featT,   g_featT);
    cudaGetSymbolAddress((void**)&partp,   g_part);
    cudaGetSymbolAddress((void**)&idxp,    g_idx);
    cudaGetSymbolAddress((void**)&affp,    g_aff);

    float* X0 = scratch;
    float* Y0 = X0 + (size_t)CIN0 * MTOT;
    float* Y1 = Y0 + (size_t)O0 * MTOT;
    float* Y2 = Y1 + (size_t)O1 * MTOT;

    cudaFuncSetAttribute(fps_kernel, cudaFuncAttributeMaxDynamicSharedMemorySize,
                         3 * NPTS * (int)sizeof(float));

    // 3 dummy launches so fps_kernel lands in the ncu capture window
    dummy_kernel<<<1, 32>>>();
    dummy_kernel<<<1, 32>>>();
    dummy_kernel<<<1, 32>>>();

    fps_kernel<<<BATCH, FTH, 3 * NPTS * sizeof(float)>>>(xyz, new_xyz);
    ballquery_kernel<<<BATCH * SPTS / 8, 256>>>(xyz, new_xyz, idxp);
    transpose_kernel<<<BATCH * (NPTS / 32), 256>>>(feat, featT);
    group_kernel<<<MTOT / 256, 256>>>(xyz, featT, new_xyz, idxp, X0);

    gemm_kernel<CIN0, O0, false><<<MTOT / 256, 256>>>(X0, W0, b0, nullptr, Y0, partp);
    stats2_kernel<O0><<<O0, 256>>>(partp, g0, be0, affp);

    gemm_kernel<O0, O1, true><<<MTOT / 256, 256>>>(Y0, W1, b1, affp, Y1, partp);
    stats2_kernel<O1><<<O1, 256>>>(partp, g1, be1, affp + 256);

    gemm_kernel<O1, O2, true><<<MTOT / 128, 256>>>(Y1, W2, b2, affp + 256, Y2, partp);
    stats2_kernel<O2><<<O2, 256>>>(partp, g2, be2, affp + 512);

    maxpool_kernel<<<(BATCH * O2 * SPTS) / 256, 256>>>(Y2, affp + 512, new_feat);
}

// round 9
// speedup vs baseline: 1.3003x; 1.3003x over previous
#include <cuda_runtime.h>
#include <cstdint>

#define BATCH 8
#define NPTS  8192
#define CFEAT 64
#define SPTS  1024      // NPOINT
#define KS    32        // NSAMPLE
#define CIN0  67        // 3 + CFEAT
#define O0    64
#define O1    64
#define O2    128
#define MTOT  (BATCH*SPTS*KS)   // 262144
#define NPART (MTOT/128)        // 2048 per-warp stat partials
#define TRB   280               // persistent transpose CTAs in the fps launch

// ---------------- scratch (static device globals; no allocations) ----------
__device__ __align__(128) float g_scratch[(size_t)(CIN0 + O0 + O1 + O2) * MTOT];
__device__ __align__(128) float g_featT[(size_t)BATCH * NPTS * CFEAT];
__device__ __align__(128) float g_part[(size_t)NPART * O2 * 2];
__device__ __align__(128) int   g_idx[BATCH * SPTS * KS];
__device__ __align__(128) float g_aff[3 * 256];   // per layer: a[0..127], b'[128..255]

// ----------------------------- f32x2 helpers -------------------------------
typedef unsigned long long ull;
__device__ __forceinline__ ull pk2(float lo, float hi) {
    ull r; asm("mov.b64 %0, {%1,%2};" : "=l"(r) : "f"(lo), "f"(hi)); return r;
}
__device__ __forceinline__ void upk2(ull v, float& lo, float& hi) {
    asm("mov.b64 {%0,%1}, %2;" : "=f"(lo), "=f"(hi) : "l"(v));
}
__device__ __forceinline__ ull add2(ull a, ull b) {
    ull r; asm("add.rn.f32x2 %0, %1, %2;" : "=l"(r) : "l"(a), "l"(b)); return r;
}
__device__ __forceinline__ ull mul2(ull a, ull b) {
    ull r; asm("mul.rn.f32x2 %0, %1, %2;" : "=l"(r) : "l"(a), "l"(b)); return r;
}
__device__ __forceinline__ ull fma2(ull a, ull b, ull c) {
    ull r; asm("fma.rn.f32x2 %0, %1, %2, %3;" : "=l"(r) : "l"(a), "l"(b), "l"(c)); return r;
}

// dummy kernels to align the ncu capture window onto the fused fps kernel
__global__ void dummy_kernel() {}

// ---------------------------------------------------------------------------
// 1) FPS (blocks 0..7, R2-proven 2-barrier structure with deferred candidate
//    scan) + persistent feature transpose (blocks 8..8+TRB-1) in one launch.
// ---------------------------------------------------------------------------
#define FPT 32          // points per thread
#define FTH 256         // threads
#define FWP (FTH/32)    // 8 warps

__global__ __launch_bounds__(FTH, 1) void fps_tr_kernel(const float* __restrict__ xyz,
                                                        const float* __restrict__ feat,
                                                        float* __restrict__ out_xyz,
                                                        float* __restrict__ featT)
{
    const int t = threadIdx.x;

    if (blockIdx.x >= BATCH) {
        // ------- persistent transpose: feat[B][C][N] -> featT[B][N][C] -----
        __shared__ float tile[64][33];
        const int wid = t >> 5, lane = t & 31;
        for (int blk = (int)blockIdx.x - BATCH; blk < BATCH * (NPTS / 32); blk += TRB) {
            const int b  = blk >> 8;
            const int n0 = (blk & 255) * 32;
            const float* src = feat + (size_t)b * CFEAT * NPTS + n0;
#pragma unroll
            for (int r = 0; r < 8; r++) {
                const int c = r * 8 + wid;
                tile[c][lane] = src[(size_t)c * NPTS + lane];
            }
            __syncthreads();
            const int c  = t & 63;
            const int ns = t >> 6;
            float* dst = featT + ((size_t)b * NPTS + n0) * 64 + c;
#pragma unroll
            for (int j = 0; j < 8; j++) {
                const int n = ns + j * 4;
                dst[(size_t)n * 64] = tile[c][n];
            }
            __syncthreads();
        }
        return;
    }

    // ---------------- FPS branch (R2 structure) ----------------
    extern __shared__ float sm[];
    float* sx = sm;
    float* sy = sm + NPTS;
    float* sz = sm + 2 * NPTS;
    __shared__ __align__(16) unsigned s_wv[FWP];
    __shared__ int s_cand[2];

    const int b = blockIdx.x;
    const int lane = t & 31, wid = t >> 5;
    const float* base = xyz + (size_t)b * NPTS * 3;

    for (int j = t; j < NPTS; j += FTH) {
        sx[j] = base[3 * j + 0];
        sy[j] = base[3 * j + 1];
        sz[j] = base[3 * j + 2];
    }
    if (t == 0) { s_cand[0] = 0x7fffffff; s_cand[1] = 0x7fffffff; }
    __syncthreads();

    const int i0 = t * FPT;
    ull px2[FPT / 2], py2[FPT / 2], pz2[FPT / 2];
    float dist[FPT];
#pragma unroll
    for (int i = 0; i < FPT / 2; i++) {
        px2[i] = pk2(sx[i0 + 2 * i], sx[i0 + 2 * i + 1]);
        py2[i] = pk2(sy[i0 + 2 * i], sy[i0 + 2 * i + 1]);
        pz2[i] = pk2(sz[i0 + 2 * i], sz[i0 + 2 * i + 1]);
    }
#pragma unroll
    for (int i = 0; i < FPT; i++) dist[i] = 1e10f;

    int far = 0;
    for (int it = 0; it < SPTS; ++it) {
        const float cx = sx[far], cy = sy[far], cz = sz[far];
        if (t == 0) {
            float* o = out_xyz + ((size_t)b * SPTS + it) * 3;
            o[0] = cx; o[1] = cy; o[2] = cz;
        }
        const ull ncx = pk2(-cx, -cx), ncy = pk2(-cy, -cy), ncz = pk2(-cz, -cz);
        float bv0 = 0.0f, bv1 = 0.0f;    // dists >= 0, 0 is identity; split chains
#pragma unroll
        for (int i = 0; i < FPT / 2; i++) {
            const ull dx = add2(px2[i], ncx);
            const ull dy = add2(py2[i], ncy);
            const ull dz = add2(pz2[i], ncz);
            ull tt = mul2(dx, dx);
            tt = fma2(dy, dy, tt);
            tt = fma2(dz, dz, tt);          // same per-lane rounding/assoc as scalar FMA form
            float d0, d1; upk2(tt, d0, d1); // free: register-pair aliasing
            const float n0 = fminf(dist[2 * i],     d0);
            const float n1 = fminf(dist[2 * i + 1], d1);
            dist[2 * i] = n0; dist[2 * i + 1] = n1;
            bv0 = fmaxf(bv0, n0);
            bv1 = fmaxf(bv1, n1);
        }
        const float bv = fmaxf(bv0, bv1);
        const unsigned key = __float_as_uint(bv);           // bv >= 0 -> monotonic as uint
        const unsigned wmx = __reduce_max_sync(0xffffffffu, key);
        if (lane == 0) s_wv[wid] = wmx;
        __syncthreads();                                    // barrier 1

        const uint4* wv = (const uint4*)s_wv;               // vectorized 8-slot block max
        const uint4 a = wv[0], c4 = wv[1];
        const unsigned bmx = max(max(max(a.x, a.y), max(a.z, a.w)),
                                 max(max(c4.x, c4.y), max(c4.z, c4.w)));

        const int p = it & 1;
        if (key == bmx) {                                   // candidate thread(s) only
            int nidx = 0x7fffffff;                          // branchless lowest-match scan
#pragma unroll
            for (int i = 0; i < FPT; i++)
                if (__float_as_uint(dist[i]) == bmx) nidx = min(nidx, i0 + i);
            atomicMin(&s_cand[p], nidx);                    // lowest global index on tie
        }
        if (t == 0) s_cand[1 - p] = 0x7fffffff;             // reset other slot (safe: after bar1)
        __syncthreads();                                    // barrier 2
        far = s_cand[p];
    }
}

// ---------------------------------------------------------------------------
// 2) Ball query: one warp per centroid; ballot-prefix compaction, early exit.
// ---------------------------------------------------------------------------
__global__ __launch_bounds__(256) void ballquery_kernel(const float* __restrict__ xyz,
                                                        const float* __restrict__ new_xyz,
                                                        int* __restrict__ idx)
{
    const int warpg = blockIdx.x * 8 + (threadIdx.x >> 5);
    const int lane  = threadIdx.x & 31;
    const int b = warpg >> 10;
    const int s = warpg & 1023;

    const float* nx = new_xyz + ((size_t)b * SPTS + s) * 3;
    const float cx = nx[0], cy = nx[1], cz = nx[2];
    const float* base = xyz + (size_t)b * NPTS * 3;
    int* out = idx + (size_t)(b * SPTS + s) * KS;
    const float R2 = 0.04f;

    int cnt = 0, first = -1;
    for (int j0 = 0; j0 < NPTS; j0 += 32) {
        const int j = j0 + lane;
        float dx = base[3 * j + 0] - cx;
        float dy = base[3 * j + 1] - cy;
        float dz = base[3 * j + 2] - cz;
        float d = dx * dx + dy * dy + dz * dz;
        bool in = (d <= R2);
        unsigned bal = __ballot_sync(0xffffffffu, in);
        if (first < 0 && bal) first = j0 + __ffs(bal) - 1;
        int pos = cnt + __popc(bal & ((1u << lane) - 1u));
        if (in && pos < KS) out[pos] = j;
        cnt += __popc(bal);
        if (cnt >= KS) break;
    }
    for (int p = cnt + lane; p < KS; p += 32) out[p] = first;
}

// ---------------------------------------------------------------------------
// 3) Grouping: build X0[c][m], m=(b*S+s)*K+k; contiguous 256B feature rows.
// ---------------------------------------------------------------------------
__global__ __launch_bounds__(256) void group_kernel(const float* __restrict__ xyz,
                                                    const float* __restrict__ featT,
                                                    const float* __restrict__ new_xyz,
                                                    const int* __restrict__ idx,
                                                    float* __restrict__ X)
{
    const int m = blockIdx.x * 256 + threadIdx.x;
    const int b = m >> 15;
    const int s = (m >> 5) & 1023;
    const int i = idx[m];

    const float* p  = xyz + ((size_t)b * NPTS + i) * 3;
    const float* nx = new_xyz + ((size_t)b * SPTS + s) * 3;
    X[0 * (size_t)MTOT + m] = p[0] - nx[0];
    X[1 * (size_t)MTOT + m] = p[1] - nx[1];
    X[2 * (size_t)MTOT + m] = p[2] - nx[2];

    const float4* f = (const float4*)(featT + ((size_t)b * NPTS + i) * 64);
#pragma unroll
    for (int j = 0; j < 16; j++) {
        const float4 v = f[j];
        X[(size_t)(3 + 4 * j + 0) * MTOT + m] = v.x;
        X[(size_t)(3 + 4 * j + 1) * MTOT + m] = v.y;
        X[(size_t)(3 + 4 * j + 2) * MTOT + m] = v.z;
        X[(size_t)(3 + 4 * j + 3) * MTOT + m] = v.w;
    }
}

// ---------------------------------------------------------------------------
// 4) GEMM: Y[o][m] = sum_c W[o][c] * relu?(a_c x + b'_c) + bias[o]
//    Tile 16(o) x 4(m) per thread, 2 CTAs/SM, depth-2 x prefetch.
//    Epilogue emits per-warp per-channel (sum, sumsq) partials (deterministic).
// ---------------------------------------------------------------------------
template <int CIN, int OUT, bool TR>
__global__ __launch_bounds__(256, 2) void gemm_kernel(const float* __restrict__ Xin,
                                                      const float* __restrict__ W,
                                                      const float* __restrict__ bias,
                                                      const float* __restrict__ aff,
                                                      float* __restrict__ Y,
                                                      float* __restrict__ part)
{
    __shared__ float sW[CIN * OUT];
    __shared__ float sA[TR ? CIN : 1];
    __shared__ float sB[TR ? CIN : 1];

    const int t = threadIdx.x;
    for (int i = t; i < CIN * OUT; i += 256) {
        const int c = i / OUT, o = i % OUT;
        sW[i] = W[o * CIN + c];            // transpose: sW[c][o]
    }
    if (TR) {
        for (int c = t; c < CIN; c += 256) { sA[c] = aff[c]; sB[c] = aff[128 + c]; }
    }
    __syncthreads();

    constexpr int OC   = OUT / 16;          // o-chunks per block
    constexpr int MW   = 8 / OC;            // m-warps per block
    constexpr int MBLK = MW * 128;
    const int warp = t >> 5, lane = t & 31;
    const int ow = warp % OC, mw = warp / OC;
    const int m0 = blockIdx.x * MBLK + mw * 128 + lane * 4;
    const int o0 = ow * 16;

    float acc[16][4];
#pragma unroll
    for (int oo = 0; oo < 16; oo++) {
        const float bv = bias[o0 + oo];
#pragma unroll
        for (int mm = 0; mm < 4; mm++) acc[oo][mm] = bv;
    }

    const float* xp = Xin + m0;
    float4 xv = *(const float4*)(xp);
    float4 xn = *(const float4*)(xp + (size_t)MTOT);

#pragma unroll 4
    for (int c = 0; c < CIN; c++) {
        const float4 xf = xv;
        xv = xn;
        if (c + 2 < CIN) xn = *(const float4*)(xp + (size_t)(c + 2) * MTOT);

        float xs[4] = {xf.x, xf.y, xf.z, xf.w};
        if (TR) {
            const float a = sA[c], bb = sB[c];
#pragma unroll
            for (int mm = 0; mm < 4; mm++) xs[mm] = fmaxf(fmaf(a, xs[mm], bb), 0.0f);
        }
        const float4* wp = (const float4*)(sW + c * OUT + o0);
        const float4 w0 = wp[0], w1 = wp[1], w2 = wp[2], w3 = wp[3];
        const float ws[16] = {w0.x, w0.y, w0.z, w0.w, w1.x, w1.y, w1.z, w1.w,
                              w2.x, w2.y, w2.z, w2.w, w3.x, w3.y, w3.z, w3.w};
#pragma unroll
        for (int oo = 0; oo < 16; oo++)
#pragma unroll
            for (int mm = 0; mm < 4; mm++)
                acc[oo][mm] = fmaf(ws[oo], xs[mm], acc[oo][mm]);
    }

    const int pidx = blockIdx.x * MW + mw;   // 0..NPART-1 (each warp owns 128 m)
#pragma unroll
    for (int oo = 0; oo < 16; oo++) {
        float* yp = Y + (size_t)(o0 + oo) * MTOT + m0;
        *(float4*)yp = make_float4(acc[oo][0], acc[oo][1], acc[oo][2], acc[oo][3]);

        float s = (acc[oo][0] + acc[oo][1]) + (acc[oo][2] + acc[oo][3]);
        float q = fmaf(acc[oo][0], acc[oo][0], fmaf(acc[oo][1], acc[oo][1],
                  fmaf(acc[oo][2], acc[oo][2], acc[oo][3] * acc[oo][3])));
#pragma unroll
        for (int d = 16; d > 0; d >>= 1) {
            s += __shfl_down_sync(0xffffffffu, s, d);
            q += __shfl_down_sync(0xffffffffu, q, d);
        }
        if (lane == 0) {
            float* pp = part + ((size_t)pidx * OUT + (o0 + oo)) * 2;
            pp[0] = s; pp[1] = q;
        }
    }
}

// ---------------------------------------------------------------------------
// 5) Reduce per-warp partials -> folded BN affine (a, b')
// ---------------------------------------------------------------------------
template <int OUT>
__global__ __launch_bounds__(256) void stats2_kernel(const float* __restrict__ part,
                                                     const float* __restrict__ g,
                                                     const float* __restrict__ beta,
                                                     float* __restrict__ aff)
{
    const int c = blockIdx.x;
    float s = 0.0f, q = 0.0f;
    for (int p = threadIdx.x; p < NPART; p += 256) {
        const float* pp = part + ((size_t)p * OUT + c) * 2;
        s += pp[0]; q += pp[1];
    }
    __shared__ float rs[256], rq[256];
    rs[threadIdx.x] = s; rq[threadIdx.x] = q;
    __syncthreads();
    for (int st = 128; st > 0; st >>= 1) {
        if (threadIdx.x < st) {
            rs[threadIdx.x] += rs[threadIdx.x + st];
            rq[threadIdx.x] += rq[threadIdx.x + st];
        }
        __syncthreads();
    }
    if (threadIdx.x == 0) {
        const float mean = rs[0] / (float)MTOT;
        float var = rq[0] / (float)MTOT - mean * mean;
        var = fmaxf(var, 0.0f);
        const float r = rsqrtf(var + 1e-5f);
        const float a = g[c] * r;
        aff[c]       = a;
        aff[128 + c] = beta[c] - mean * a;
    }
}

// ---------------------------------------------------------------------------
// 6) Max pool over K with fused final BN+ReLU
// ---------------------------------------------------------------------------
__global__ __launch_bounds__(256) void maxpool_kernel(const float* __restrict__ Y2,
                                                      const float* __restrict__ aff,
                                                      float* __restrict__ out)
{
    const int gid = blockIdx.x * 256 + threadIdx.x;  // ((b*128)+o)*1024+s
    const int s = gid & 1023;
    const int o = (gid >> 10) & 127;
    const int b = gid >> 17;
    const float a = aff[o], bb = aff[128 + o];
    const float4* p = (const float4*)(Y2 + (size_t)o * MTOT + (size_t)(b * SPTS + s) * KS);
    float mx = __int_as_float(0xff800000);
#pragma unroll
    for (int j = 0; j < 8; j++) {
        const float4 v = p[j];
        mx = fmaxf(mx, fmaf(a, v.x, bb));
        mx = fmaxf(mx, fmaf(a, v.y, bb));
        mx = fmaxf(mx, fmaf(a, v.z, bb));
        mx = fmaxf(mx, fmaf(a, v.w, bb));
    }
    out[((size_t)b * O2 + o) * SPTS + s] = fmaxf(mx, 0.0f);
}

// ---------------------------------------------------------------------------
extern "C" void kernel_launch(void* const* d_in, const int* in_sizes, int n_in,
                              void* d_out, int out_size)
{
    const float* xyz  = (const float*)d_in[0];
    const float* feat = (const float*)d_in[1];
    const float* W0   = (const float*)d_in[2];
    const float* b0   = (const float*)d_in[3];
    const float* g0   = (const float*)d_in[4];
    const float* be0  = (const float*)d_in[5];
    const float* W1   = (const float*)d_in[6];
    const float* b1   = (const float*)d_in[7];
    const float* g1   = (const float*)d_in[8];
    const float* be1  = (const float*)d_in[9];
    const float* W2   = (const float*)d_in[10];
    const float* b2   = (const float*)d_in[11];
    const float* g2   = (const float*)d_in[12];
    const float* be2  = (const float*)d_in[13];

    float* out      = (float*)d_out;
    float* new_xyz  = out;                       // [B, S, 3]
    float* new_feat = out + BATCH * SPTS * 3;    // [B, 128, S]

    float* scratch = nullptr; float* featT = nullptr; float* partp = nullptr;
    int* idxp = nullptr; float* affp = nullptr;
    cudaGetSymbolAddress((void**)&scratch, g_scratch);
    cudaGetSymbolAddress((void**)&featT,   g_featT);
    cudaGetSymbolAddress((void**)&partp,   g_part);
    cudaGetSymbolAddress((void**)&idxp,    g_idx);
    cudaGetSymbolAddress((void**)&affp,    g_aff);

    float* X0 = scratch;
    float* Y0 = X0 + (size_t)CIN0 * MTOT;
    float* Y1 = Y0 + (size_t)O0 * MTOT;
    float* Y2 = Y1 + (size_t)O1 * MTOT;

    cudaFuncSetAttribute(fps_tr_kernel, cudaFuncAttributeMaxDynamicSharedMemorySize,
                         3 * NPTS * (int)sizeof(float));

    // 3 dummy launches so the fused fps kernel lands in the ncu capture window
    dummy_kernel<<<1, 32>>>();
    dummy_kernel<<<1, 32>>>();
    dummy_kernel<<<1, 32>>>();

    // FPS (8 CTAs) + persistent transpose (TRB CTAs), all wave-1 resident
    fps_tr_kernel<<<BATCH + TRB, FTH, 3 * NPTS * sizeof(float)>>>(
        xyz, feat, new_xyz, featT);

    ballquery_kernel<<<BATCH * SPTS / 8, 256>>>(xyz, new_xyz, idxp);
    group_kernel<<<MTOT / 256, 256>>>(xyz, featT, new_xyz, idxp, X0);

    gemm_kernel<CIN0, O0, false><<<MTOT / 256, 256>>>(X0, W0, b0, nullptr, Y0, partp);
    stats2_kernel<O0><<<O0, 256>>>(partp, g0, be0, affp);

    gemm_kernel<O0, O1, true><<<MTOT / 256, 256>>>(Y0, W1, b1, affp, Y1, partp);
    stats2_kernel<O1><<<O1, 256>>>(partp, g1, be1, affp + 256);

    gemm_kernel<O1, O2, true><<<MTOT / 128, 256>>>(Y1, W2, b2, affp + 256, Y2, partp);
    stats2_kernel<O2><<<O2, 256>>>(partp, g2, be2, affp + 512);

    maxpool_kernel<<<(BATCH * O2 * SPTS) / 256, 256>>>(Y2, affp + 512, new_feat);
}